// round 11
// baseline (speedup 1.0000x reference)
#include <cuda_runtime.h>
#include <cuda_bf16.h>
#include <cstdint>

// Problem constants: B=4, N=256, D=128, M=128, C=128
#define BB 4
#define NN 256
#define DD 128
#define MM 128
#define CC 128

// Scratch (device globals — no allocation allowed)
// g_pi/g_pjb PRE-SCALED by 0.5 so hx = g_pi + g_pjb = pre/2; silu(pre)=hx+hx*tanh(hx)
__device__ float g_pi[BB * NN * MM];
__device__ float g_pjb[BB * NN * MM];
__device__ float g_W2c[MM * MM];        // W2 @ Wc1
__device__ float g_b2c[MM];             // b2 @ Wc1
__device__ float g_part[2][BB * NN * MM];  // partial weighted-silu sums per j-half

__device__ __forceinline__ float tanh_approx(float x) {
    float y;
    asm("tanh.approx.f32 %0, %1;" : "=f"(y) : "f"(x));
    return y;
}
__device__ __forceinline__ float siluf(float x) {
    return __fdividef(x, 1.0f + __expf(-x));
}
__device__ __forceinline__ void cp16(unsigned int dst, const float* src) {
    asm volatile("cp.async.cg.shared.global [%0], [%1], 16;" :: "r"(dst), "l"(src));
}
#define CP_COMMIT()   asm volatile("cp.async.commit_group;")
#define CP_WAIT(n)    asm volatile("cp.async.wait_group %0;" :: "n"(n))

// ---------------------------------------------------------------------------
// Prep kernel: 321 blocks x 256 threads (unchanged — known good).
// ---------------------------------------------------------------------------
__global__ void __launch_bounds__(256) prep_kernel(
    const float* __restrict__ h,
    const float* __restrict__ W1a,
    const float* __restrict__ W1b,
    const float* __restrict__ b1,
    const float* __restrict__ W2,
    const float* __restrict__ b2,
    const float* __restrict__ Wc1)
{
    const int t = threadIdx.x;

    if (blockIdx.x < 256) {
        const int row0 = blockIdx.x * 4;
        const int col  = t & 127;
        const int rh   = (t >> 7) * 2;

        __shared__ float hsh[4][DD];
        #pragma unroll
        for (int k = 0; k < 2; k++) {
            int idx = k * 256 + t;
            hsh[idx >> 7][idx & 127] = h[(size_t)row0 * DD + idx];
        }
        __syncthreads();

        float a0 = 0.f, a1 = 0.f, p0 = 0.f, p1 = 0.f;
        #pragma unroll 8
        for (int d = 0; d < DD; d++) {
            const float wa = W1a[d * MM + col];
            const float wb = W1b[d * MM + col];
            const float h0 = hsh[rh][d];
            const float h1 = hsh[rh + 1][d];
            a0 = fmaf(h0, wa, a0);
            a1 = fmaf(h1, wa, a1);
            p0 = fmaf(h0, wb, p0);
            p1 = fmaf(h1, wb, p1);
        }
        const float bb = b1[col];
        const int r0 = row0 + rh;
        g_pi[(size_t)r0 * MM + col]        = 0.5f * a0;
        g_pi[(size_t)(r0 + 1) * MM + col]  = 0.5f * a1;
        g_pjb[(size_t)r0 * MM + col]       = 0.5f * (p0 + bb);
        g_pjb[(size_t)(r0 + 1) * MM + col] = 0.5f * (p1 + bb);
    } else if (blockIdx.x < 320) {
        const int m  = (blockIdx.x - 256) * 2 + (t >> 7);
        const int k  = t & 127;

        __shared__ float w2row[2][MM];
        w2row[t >> 7][k] = W2[m * MM + k];
        __syncthreads();

        float v0 = 0.f, v1 = 0.f;
        #pragma unroll 8
        for (int l = 0; l < MM; l += 2) {
            v0 = fmaf(w2row[t >> 7][l],     Wc1[l * MM + k],       v0);
            v1 = fmaf(w2row[t >> 7][l + 1], Wc1[(l + 1) * MM + k], v1);
        }
        g_W2c[m * MM + k] = v0 + v1;
    } else {
        if (t < MM) {
            float v = 0.f;
            #pragma unroll 8
            for (int l = 0; l < MM; l++)
                v = fmaf(b2[l], Wc1[l * MM + t], v);
            g_b2c[t] = v;
        }
    }
}

// ---------------------------------------------------------------------------
// Main kernel: 1024 blocks = (b, i-pair, j-half). 256 threads = 8 warps.
// Each warp: 16 j-rows via per-warp cp.async ring (5 slots, distance 4,
// fully unrolled, no mainloop barriers). Each row feeds BOTH i's.
// Partial sums written to g_part[half] (no atomics -> deterministic).
// Acc-reduction smem OVERLAYS the ring (sync'ed) to keep smem ~21KB.
// ---------------------------------------------------------------------------
__global__ void __launch_bounds__(256) main_kernel(const float* __restrict__ adj)
{
    const int blk = blockIdx.x;         // 0..1023
    const int hh  = blk & 1;            // j-half
    const int bp  = blk >> 1;           // 0..511
    const int b   = bp >> 7;
    const int i0  = (bp & 127) * 2;
    const int t   = threadIdx.x;
    const int lane = t & 31;
    const int w    = t >> 5;

    __shared__ float4 ring[8][5][32];   // 20KB; later overlaid by acc buffer
    __shared__ float adjsh[2][128];

    // adj weights for this j-half, both i's, diagonal folded to 0
    {
        const int c     = t & 127;
        const int which = t >> 7;
        const int j     = hh * 128 + c;
        float v = adj[((size_t)(b * NN + i0 + which)) * NN + j];
        if (j == i0 + which) v = 0.f;
        adjsh[which][c] = v;
    }
    __syncthreads();

    const float4 piA = *reinterpret_cast<const float4*>(
        g_pi + ((size_t)(b * NN + i0)) * MM + lane * 4);
    const float4 piB = *reinterpret_cast<const float4*>(
        g_pi + ((size_t)(b * NN + i0 + 1)) * MM + lane * 4);

    // warp w's rows: j_local = w + 8*jo (jo = 0..15)
    const float* base = g_pjb + (size_t)b * NN * MM
                        + (size_t)(hh * 128 + w) * MM + lane * 4;

    const unsigned int ring_lane =
        (unsigned int)__cvta_generic_to_shared(&ring[w][0][lane]);
    const float4* ring_rd = &ring[w][0][lane];   // slot stride = 32 float4
    const float*  adjA = adjsh[0] + w;
    const float*  adjB = adjsh[1] + w;

    float4 accA = make_float4(0.f, 0.f, 0.f, 0.f);
    float4 accB = make_float4(0.f, 0.f, 0.f, 0.f);

    // Prologue: 4 rows in flight
    #pragma unroll
    for (int r = 0; r < 4; r++) {
        cp16(ring_lane + (unsigned int)(r * 512), base + 8 * r * MM);
        CP_COMMIT();
    }

    // Steady state: rows 0..11, prefetch rows 4..15 (slot (jo+4)%5)
    #pragma unroll
    for (int jo = 0; jo < 12; jo++) {
        CP_WAIT(3);
        const float4 v = ring_rd[(jo % 5) * 32];
        const float w0 = adjA[8 * jo];
        const float w1 = adjB[8 * jo];
        {
            float hx0 = piA.x + v.x, hx1 = piA.y + v.y;
            float hx2 = piA.z + v.z, hx3 = piA.w + v.w;
            float s0 = fmaf(hx0, tanh_approx(hx0), hx0);
            float s1 = fmaf(hx1, tanh_approx(hx1), hx1);
            float s2 = fmaf(hx2, tanh_approx(hx2), hx2);
            float s3 = fmaf(hx3, tanh_approx(hx3), hx3);
            accA.x = fmaf(w0, s0, accA.x);
            accA.y = fmaf(w0, s1, accA.y);
            accA.z = fmaf(w0, s2, accA.z);
            accA.w = fmaf(w0, s3, accA.w);
        }
        {
            float hx0 = piB.x + v.x, hx1 = piB.y + v.y;
            float hx2 = piB.z + v.z, hx3 = piB.w + v.w;
            float s0 = fmaf(hx0, tanh_approx(hx0), hx0);
            float s1 = fmaf(hx1, tanh_approx(hx1), hx1);
            float s2 = fmaf(hx2, tanh_approx(hx2), hx2);
            float s3 = fmaf(hx3, tanh_approx(hx3), hx3);
            accB.x = fmaf(w1, s0, accB.x);
            accB.y = fmaf(w1, s1, accB.y);
            accB.z = fmaf(w1, s2, accB.z);
            accB.w = fmaf(w1, s3, accB.w);
        }
        cp16(ring_lane + (unsigned int)(((jo + 4) % 5) * 512),
             base + 8 * (jo + 4) * MM);
        CP_COMMIT();
    }

    // Drain: rows 12..15
    CP_WAIT(0);
    #pragma unroll
    for (int jo = 12; jo < 16; jo++) {
        const float4 v = ring_rd[(jo % 5) * 32];
        const float w0 = adjA[8 * jo];
        const float w1 = adjB[8 * jo];
        {
            float hx0 = piA.x + v.x, hx1 = piA.y + v.y;
            float hx2 = piA.z + v.z, hx3 = piA.w + v.w;
            float s0 = fmaf(hx0, tanh_approx(hx0), hx0);
            float s1 = fmaf(hx1, tanh_approx(hx1), hx1);
            float s2 = fmaf(hx2, tanh_approx(hx2), hx2);
            float s3 = fmaf(hx3, tanh_approx(hx3), hx3);
            accA.x = fmaf(w0, s0, accA.x);
            accA.y = fmaf(w0, s1, accA.y);
            accA.z = fmaf(w0, s2, accA.z);
            accA.w = fmaf(w0, s3, accA.w);
        }
        {
            float hx0 = piB.x + v.x, hx1 = piB.y + v.y;
            float hx2 = piB.z + v.z, hx3 = piB.w + v.w;
            float s0 = fmaf(hx0, tanh_approx(hx0), hx0);
            float s1 = fmaf(hx1, tanh_approx(hx1), hx1);
            float s2 = fmaf(hx2, tanh_approx(hx2), hx2);
            float s3 = fmaf(hx3, tanh_approx(hx3), hx3);
            accB.x = fmaf(w1, s0, accB.x);
            accB.y = fmaf(w1, s1, accB.y);
            accB.z = fmaf(w1, s2, accB.z);
            accB.w = fmaf(w1, s3, accB.w);
        }
    }

    // All ring reads done -> safe to overlay the acc-reduction buffer
    __syncthreads();
    float* accsh = reinterpret_cast<float*>(ring);   // [8][2][MM] = 8KB
    {
        float* myacc = accsh + w * 2 * MM;
        *reinterpret_cast<float4*>(myacc + lane * 4)      = accA;
        *reinterpret_cast<float4*>(myacc + MM + lane * 4) = accB;
    }
    __syncthreads();

    // Reduce across warps and write partial: thread -> (ii = t>>7, col)
    const int ii  = t >> 7;
    const int col = t & 127;
    float s = 0.f;
    #pragma unroll
    for (int g = 0; g < 8; g++) s += accsh[g * 2 * MM + ii * MM + col];
    g_part[hh][((size_t)(b * NN + i0 + ii)) * MM + col] = s;
}

// ---------------------------------------------------------------------------
// Epilogue kernel: 512 blocks = (b, i-pair). 256 threads.
// Combines partials, computes S/denominator from adj, runs the two
// coalesced matvecs (W2@Wc1 pre-folded).
// ---------------------------------------------------------------------------
__global__ void __launch_bounds__(256) epi_kernel(
    const float* __restrict__ adj,
    const float* __restrict__ bc1,
    const float* __restrict__ Wc2,
    const float* __restrict__ bc2,
    float* __restrict__ out)
{
    const int bp = blockIdx.x;          // 0..511
    const int b  = bp >> 7;
    const int i0 = (bp & 127) * 2;
    const int t  = threadIdx.x;
    const int lane = t & 31;
    const int w    = t >> 5;

    __shared__ float wsum[2][8];
    __shared__ float sacc[2][MM];
    __shared__ float shid[2][MM];

    const float* arow0 = adj + ((size_t)(b * NN + i0)) * NN;
    const float* arow1 = arow0 + NN;
    float a0 = arow0[t], a1 = arow1[t];
    const float ii0 = arow0[i0];
    const float ii1 = arow1[i0 + 1];
    #pragma unroll
    for (int o = 16; o; o >>= 1) {
        a0 += __shfl_xor_sync(0xFFFFFFFFu, a0, o);
        a1 += __shfl_xor_sync(0xFFFFFFFFu, a1, o);
    }
    if (lane == 0) { wsum[0][w] = a0; wsum[1][w] = a1; }

    // Combine partials while the adj reduction lands
    const int ii  = t >> 7;
    const int col = t & 127;
    const size_t idx = ((size_t)(b * NN + i0 + ii)) * MM + col;
    sacc[ii][col] = g_part[0][idx] + g_part[1][idx];
    __syncthreads();

    float sum0 = 0.f, sum1 = 0.f;
    #pragma unroll
    for (int g = 0; g < 8; g++) { sum0 += wsum[0][g]; sum1 += wsum[1][g]; }
    const float S0   = sum0 - ii0;
    const float S1   = sum1 - ii1;
    const float inv0 = __fdividef(1.0f, fmaxf(sum0, 1.0f));
    const float inv1 = __fdividef(1.0f, fmaxf(sum1, 1.0f));
    const float Si   = ii ? S1 : S0;
    const float invi = ii ? inv1 : inv0;

    // Stage 1: hid = silu((sacc @ W2c + S*b2c)*inv_d + bc1)  (coalesced cols)
    {
        const float* s = sacc[ii];
        float v0 = 0.f, v1 = 0.f, v2 = 0.f, v3 = 0.f;
        #pragma unroll 8
        for (int m2 = 0; m2 < MM; m2 += 4) {
            v0 = fmaf(s[m2],     g_W2c[m2 * MM + col],       v0);
            v1 = fmaf(s[m2 + 1], g_W2c[(m2 + 1) * MM + col], v1);
            v2 = fmaf(s[m2 + 2], g_W2c[(m2 + 2) * MM + col], v2);
            v3 = fmaf(s[m2 + 3], g_W2c[(m2 + 3) * MM + col], v3);
        }
        const float u = fmaf((v0 + v1) + (v2 + v3) + Si * g_b2c[col], invi, bc1[col]);
        shid[ii][col] = siluf(u);
    }
    __syncthreads();

    // Stage 2: out = hid @ Wc2 + bc2 (coalesced)
    {
        const float* hd = shid[ii];
        float v0 = bc2[col], v1 = 0.f, v2 = 0.f, v3 = 0.f;
        #pragma unroll 8
        for (int m2 = 0; m2 < MM; m2 += 4) {
            v0 = fmaf(hd[m2],     Wc2[m2 * CC + col],       v0);
            v1 = fmaf(hd[m2 + 1], Wc2[(m2 + 1) * CC + col], v1);
            v2 = fmaf(hd[m2 + 2], Wc2[(m2 + 2) * CC + col], v2);
            v3 = fmaf(hd[m2 + 3], Wc2[(m2 + 3) * CC + col], v3);
        }
        out[((size_t)(b * NN + i0 + ii)) * CC + col] = (v0 + v1) + (v2 + v3);
    }
}

// ---------------------------------------------------------------------------
// Launch
// ---------------------------------------------------------------------------
extern "C" void kernel_launch(void* const* d_in, const int* in_sizes, int n_in,
                              void* d_out, int out_size)
{
    const float* h   = (const float*)d_in[0];
    const float* adj = (const float*)d_in[1];
    const float* W1a = (const float*)d_in[2];
    const float* W1b = (const float*)d_in[3];
    const float* b1  = (const float*)d_in[4];
    const float* W2  = (const float*)d_in[5];
    const float* b2  = (const float*)d_in[6];
    const float* Wc1 = (const float*)d_in[7];
    const float* bc1 = (const float*)d_in[8];
    const float* Wc2 = (const float*)d_in[9];
    const float* bc2 = (const float*)d_in[10];
    float* out = (float*)d_out;

    prep_kernel<<<321, 256>>>(h, W1a, W1b, b1, W2, b2, Wc1);
    main_kernel<<<BB * NN * 2 / 2, 256>>>(adj);   // 1024 blocks
    epi_kernel<<<BB * NN / 2, 256>>>(adj, bc1, Wc2, bc2, out);
}

// round 12
// speedup vs baseline: 1.0515x; 1.0515x over previous
#include <cuda_runtime.h>
#include <cuda_fp16.h>
#include <cstdint>

// Problem constants: B=4, N=256, D=128, M=128, C=128
#define BB 4
#define NN 256
#define DD 128
#define MM 128
#define CC 128

// Scratch (device globals — no allocation allowed)
// g_pi/g_pjb PRE-SCALED by 0.5 and stored as __half:
// hx = pi + pjb = pre/2 ; silu(pre) = hx + hx*tanh(hx)
__device__ __align__(16) __half g_pi[BB * NN * MM];
__device__ __align__(16) __half g_pjb[BB * NN * MM];
__device__ float g_W2c[MM * MM];             // W2 @ Wc1  (fp32)
__device__ float g_b2c[MM];                  // b2 @ Wc1
__device__ float g_part[2][BB * NN * MM];    // fp32 partial sums per j-half

__device__ __forceinline__ __half2 tanh2(__half2 x) {
    unsigned r, i = *reinterpret_cast<unsigned*>(&x);
    asm("tanh.approx.f16x2 %0, %1;" : "=r"(r) : "r"(i));
    return *reinterpret_cast<__half2*>(&r);
}
__device__ __forceinline__ float siluf(float x) {
    return __fdividef(x, 1.0f + __expf(-x));
}
__device__ __forceinline__ void cp16(unsigned int dst, const void* src) {
    asm volatile("cp.async.cg.shared.global [%0], [%1], 16;" :: "r"(dst), "l"(src));
}
#define CP_COMMIT()   asm volatile("cp.async.commit_group;")
#define CP_WAIT(n)    asm volatile("cp.async.wait_group %0;" :: "n"(n))

// ---------------------------------------------------------------------------
// Prep kernel: 289 blocks x 512 threads.
//  [0,256):   projection, 4 rows/block, thread = (row = t>>7, col = t&127)
//  [256,288): W2c = W2 @ Wc1, 4 m-rows/block
//  288:       b2c = b2 @ Wc1
// ---------------------------------------------------------------------------
__global__ void __launch_bounds__(512) prep_kernel(
    const float* __restrict__ h,
    const float* __restrict__ W1a,
    const float* __restrict__ W1b,
    const float* __restrict__ b1,
    const float* __restrict__ W2,
    const float* __restrict__ b2,
    const float* __restrict__ Wc1)
{
    const int t  = threadIdx.x;
    const int rg = t >> 7;        // row group 0..3
    const int col = t & 127;

    if (blockIdx.x < 256) {
        const int row = blockIdx.x * 4 + rg;

        __shared__ float hsh[4][DD];
        hsh[rg][col] = h[(size_t)blockIdx.x * 512 + t];   // coalesced: 4 rows
        __syncthreads();

        float a = 0.f, p = 0.f;
        #pragma unroll 8
        for (int d = 0; d < DD; d++) {
            const float hv = hsh[rg][d];
            a = fmaf(hv, W1a[d * MM + col], a);
            p = fmaf(hv, W1b[d * MM + col], p);
        }
        g_pi[(size_t)row * MM + col]  = __float2half(0.5f * a);
        g_pjb[(size_t)row * MM + col] = __float2half(0.5f * (p + b1[col]));
    } else if (blockIdx.x < 288) {
        const int m = (blockIdx.x - 256) * 4 + rg;

        __shared__ float w2row[4][MM];
        w2row[rg][col] = W2[m * MM + col];
        __syncthreads();

        float v0 = 0.f, v1 = 0.f;
        #pragma unroll 8
        for (int l = 0; l < MM; l += 2) {
            v0 = fmaf(w2row[rg][l],     Wc1[l * MM + col],       v0);
            v1 = fmaf(w2row[rg][l + 1], Wc1[(l + 1) * MM + col], v1);
        }
        g_W2c[m * MM + col] = v0 + v1;
    } else {
        if (t < MM) {
            float v = 0.f;
            #pragma unroll 8
            for (int l = 0; l < MM; l++)
                v = fmaf(b2[l], Wc1[l * MM + t], v);
            g_b2c[t] = v;
        }
    }
}

// ---------------------------------------------------------------------------
// Main kernel: 1024 blocks = (b, i-pair, j-half). 256 threads = 8 warps.
// Warp w owns 16 CONSECUTIVE rows [w*16, w*16+16) of its 128-row j-half.
// fp16 rows (256B): one cp16 per lane loads TWO rows per ring slot (512B).
// 4-slot per-warp ring, distance-3 prefetch, fully unrolled, no barriers.
// Each row feeds BOTH i's. fp32 accumulation. Partials -> g_part[half].
// ---------------------------------------------------------------------------
__global__ void __launch_bounds__(256) main_kernel(const float* __restrict__ adj)
{
    const int blk = blockIdx.x;         // 0..1023
    const int hh  = blk & 1;            // j-half
    const int bp  = blk >> 1;           // 0..511
    const int b   = bp >> 7;
    const int i0  = (bp & 127) * 2;
    const int t   = threadIdx.x;
    const int lane = t & 31;
    const int w    = t >> 5;

    __shared__ uint4 ring4[8][4][32];   // 16KB; overlaid by acc buffer later
    __shared__ float adjsh[2][128];

    // adj weights for this j-half, both i's, diagonal folded to 0
    {
        const int c     = t & 127;
        const int which = t >> 7;
        const int j     = hh * 128 + c;
        float v = adj[((size_t)(b * NN + i0 + which)) * NN + j];
        if (j == i0 + which) v = 0.f;
        adjsh[which][c] = v;
    }
    __syncthreads();

    // pi for both i's: 4 halfs (one 8B read) per lane -> 2 half2
    __half2 piA0, piA1, piB0, piB1;
    {
        const unsigned long long* pA = reinterpret_cast<const unsigned long long*>(
            g_pi + ((size_t)(b * NN + i0)) * MM);
        const unsigned long long* pB = reinterpret_cast<const unsigned long long*>(
            g_pi + ((size_t)(b * NN + i0 + 1)) * MM);
        unsigned long long ra = pA[lane], rb = pB[lane];
        piA0 = *reinterpret_cast<__half2*>(&ra);
        piA1 = *(reinterpret_cast<__half2*>(&ra) + 1);
        piB0 = *reinterpret_cast<__half2*>(&rb);
        piB1 = *(reinterpret_cast<__half2*>(&rb) + 1);
    }

    // cp.async source: warp w's rows start at hh*128 + w*16.
    // lane<16 covers row 2*it (+0), lane>=16 covers row 2*it+1; 8 halfs each.
    const __half* srcbase = g_pjb + ((size_t)b * NN + hh * 128 + w * 16) * MM
                            + (lane >> 4) * MM + (lane & 15) * 8;

    const unsigned int ring_lane =
        (unsigned int)__cvta_generic_to_shared(&ring4[w][0][0]) + lane * 16;
    const unsigned long long* rd =
        reinterpret_cast<const unsigned long long*>(&ring4[w][0][0]);
    const float* adjA = adjsh[0] + w * 16;
    const float* adjB = adjsh[1] + w * 16;

    float4 accA = make_float4(0.f, 0.f, 0.f, 0.f);
    float4 accB = make_float4(0.f, 0.f, 0.f, 0.f);

    // Prologue: 3 slots (6 rows) in flight
    #pragma unroll
    for (int s = 0; s < 3; s++) {
        cp16(ring_lane + s * 512, srcbase + s * 256);
        CP_COMMIT();
    }

    // 8 iterations x 2 rows, fully unrolled
    #pragma unroll
    for (int it = 0; it < 8; it++) {
        if (it < 6)      { CP_WAIT(2); }
        else if (it == 6){ CP_WAIT(1); }
        else             { CP_WAIT(0); }

        #pragma unroll
        for (int rr = 0; rr < 2; rr++) {
            unsigned long long raw = rd[((it & 3) * 64) + rr * 32 + lane];
            const __half2 v0 = *reinterpret_cast<__half2*>(&raw);
            const __half2 v1 = *(reinterpret_cast<__half2*>(&raw) + 1);
            const float wA = adjA[2 * it + rr];
            const float wB = adjB[2 * it + rr];
            {
                __half2 hx0 = __hadd2(piA0, v0);
                __half2 hx1 = __hadd2(piA1, v1);
                __half2 s0 = __hfma2(hx0, tanh2(hx0), hx0);
                __half2 s1 = __hfma2(hx1, tanh2(hx1), hx1);
                float2 f0 = __half22float2(s0);
                float2 f1 = __half22float2(s1);
                accA.x = fmaf(wA, f0.x, accA.x);
                accA.y = fmaf(wA, f0.y, accA.y);
                accA.z = fmaf(wA, f1.x, accA.z);
                accA.w = fmaf(wA, f1.y, accA.w);
            }
            {
                __half2 hx0 = __hadd2(piB0, v0);
                __half2 hx1 = __hadd2(piB1, v1);
                __half2 s0 = __hfma2(hx0, tanh2(hx0), hx0);
                __half2 s1 = __hfma2(hx1, tanh2(hx1), hx1);
                float2 f0 = __half22float2(s0);
                float2 f1 = __half22float2(s1);
                accB.x = fmaf(wB, f0.x, accB.x);
                accB.y = fmaf(wB, f0.y, accB.y);
                accB.z = fmaf(wB, f1.x, accB.z);
                accB.w = fmaf(wB, f1.y, accB.w);
            }
        }

        // prefetch slot it+3 (rows 2*(it+3), 2*(it+3)+1)
        if (it < 5) {
            cp16(ring_lane + ((it + 3) & 3) * 512, srcbase + (it + 3) * 256);
            CP_COMMIT();
        }
    }

    // All ring reads done -> overlay acc-reduction buffer (8KB of 16KB)
    __syncthreads();
    float* accsh = reinterpret_cast<float*>(ring4);   // [8][2][MM]
    {
        float* myacc = accsh + w * 2 * MM;
        *reinterpret_cast<float4*>(myacc + lane * 4)      = accA;
        *reinterpret_cast<float4*>(myacc + MM + lane * 4) = accB;
    }
    __syncthreads();

    // Reduce across warps; write fp32 partial
    const int ii  = t >> 7;
    const int col = t & 127;
    float s = 0.f;
    #pragma unroll
    for (int g = 0; g < 8; g++) s += accsh[g * 2 * MM + ii * MM + col];
    g_part[hh][((size_t)(b * NN + i0 + ii)) * MM + col] = s;
}

// ---------------------------------------------------------------------------
// Epilogue kernel: 512 blocks = (b, i-pair). 256 threads.
// ---------------------------------------------------------------------------
__global__ void __launch_bounds__(256) epi_kernel(
    const float* __restrict__ adj,
    const float* __restrict__ bc1,
    const float* __restrict__ Wc2,
    const float* __restrict__ bc2,
    float* __restrict__ out)
{
    const int bp = blockIdx.x;          // 0..511
    const int b  = bp >> 7;
    const int i0 = (bp & 127) * 2;
    const int t  = threadIdx.x;
    const int lane = t & 31;
    const int w    = t >> 5;

    __shared__ float wsum[2][8];
    __shared__ float sacc[2][MM];
    __shared__ float shid[2][MM];

    const float* arow0 = adj + ((size_t)(b * NN + i0)) * NN;
    const float* arow1 = arow0 + NN;
    float a0 = arow0[t], a1 = arow1[t];
    const float ii0 = arow0[i0];
    const float ii1 = arow1[i0 + 1];
    #pragma unroll
    for (int o = 16; o; o >>= 1) {
        a0 += __shfl_xor_sync(0xFFFFFFFFu, a0, o);
        a1 += __shfl_xor_sync(0xFFFFFFFFu, a1, o);
    }
    if (lane == 0) { wsum[0][w] = a0; wsum[1][w] = a1; }

    const int ii  = t >> 7;
    const int col = t & 127;
    const size_t idx = ((size_t)(b * NN + i0 + ii)) * MM + col;
    sacc[ii][col] = g_part[0][idx] + g_part[1][idx];
    __syncthreads();

    float sum0 = 0.f, sum1 = 0.f;
    #pragma unroll
    for (int g = 0; g < 8; g++) { sum0 += wsum[0][g]; sum1 += wsum[1][g]; }
    const float S0   = sum0 - ii0;
    const float S1   = sum1 - ii1;
    const float inv0 = __fdividef(1.0f, fmaxf(sum0, 1.0f));
    const float inv1 = __fdividef(1.0f, fmaxf(sum1, 1.0f));
    const float Si   = ii ? S1 : S0;
    const float invi = ii ? inv1 : inv0;

    // Stage 1: hid = silu((sacc @ W2c + S*b2c)*inv_d + bc1) (coalesced cols)
    {
        const float* s = sacc[ii];
        float v0 = 0.f, v1 = 0.f, v2 = 0.f, v3 = 0.f;
        #pragma unroll 8
        for (int m2 = 0; m2 < MM; m2 += 4) {
            v0 = fmaf(s[m2],     g_W2c[m2 * MM + col],       v0);
            v1 = fmaf(s[m2 + 1], g_W2c[(m2 + 1) * MM + col], v1);
            v2 = fmaf(s[m2 + 2], g_W2c[(m2 + 2) * MM + col], v2);
            v3 = fmaf(s[m2 + 3], g_W2c[(m2 + 3) * MM + col], v3);
        }
        const float u = fmaf((v0 + v1) + (v2 + v3) + Si * g_b2c[col], invi, bc1[col]);
        shid[ii][col] = siluf(u);
    }
    __syncthreads();

    // Stage 2: out = hid @ Wc2 + bc2 (coalesced)
    {
        const float* hd = shid[ii];
        float v0 = bc2[col], v1 = 0.f, v2 = 0.f, v3 = 0.f;
        #pragma unroll 8
        for (int m2 = 0; m2 < MM; m2 += 4) {
            v0 = fmaf(hd[m2],     Wc2[m2 * CC + col],       v0);
            v1 = fmaf(hd[m2 + 1], Wc2[(m2 + 1) * CC + col], v1);
            v2 = fmaf(hd[m2 + 2], Wc2[(m2 + 2) * CC + col], v2);
            v3 = fmaf(hd[m2 + 3], Wc2[(m2 + 3) * CC + col], v3);
        }
        out[((size_t)(b * NN + i0 + ii)) * CC + col] = (v0 + v1) + (v2 + v3);
    }
}

// ---------------------------------------------------------------------------
// Launch
// ---------------------------------------------------------------------------
extern "C" void kernel_launch(void* const* d_in, const int* in_sizes, int n_in,
                              void* d_out, int out_size)
{
    const float* h   = (const float*)d_in[0];
    const float* adj = (const float*)d_in[1];
    const float* W1a = (const float*)d_in[2];
    const float* W1b = (const float*)d_in[3];
    const float* b1  = (const float*)d_in[4];
    const float* W2  = (const float*)d_in[5];
    const float* b2  = (const float*)d_in[6];
    const float* Wc1 = (const float*)d_in[7];
    const float* bc1 = (const float*)d_in[8];
    const float* Wc2 = (const float*)d_in[9];
    const float* bc2 = (const float*)d_in[10];
    float* out = (float*)d_out;

    prep_kernel<<<289, 512>>>(h, W1a, W1b, b1, W2, b2, Wc1);
    main_kernel<<<1024, 256>>>(adj);
    epi_kernel<<<512, 256>>>(adj, bc1, Wc2, bc2, out);
}

// round 13
// speedup vs baseline: 1.1119x; 1.0575x over previous
#include <cuda_runtime.h>
#include <cuda_fp16.h>
#include <cstdint>

// Problem constants: B=4, N=256, D=128, M=128, C=128
#define BB 4
#define NN 256
#define DD 128
#define MM 128
#define CC 128
#define NBLK 512

// Scratch (device globals — no allocation allowed)
// g_pi/g_pjb PRE-SCALED by 0.5, stored as __half:
// hx = pi + pjb = pre/2 ; silu(pre) = hx + hx*tanh(hx)
__device__ __align__(16) __half g_pi[BB * NN * MM];
__device__ __align__(16) __half g_pjb[BB * NN * MM];
__device__ float g_W2c[MM * MM];   // W2 @ Wc1
__device__ float g_b2c[MM];        // b2 @ Wc1

// Software grid barrier state (gen persists across graph replays; compared
// by equality against a locally captured value -> deterministic)
__device__ unsigned int g_bar_count = 0;
__device__ volatile unsigned int g_bar_gen = 0;

__device__ __forceinline__ void grid_barrier() {
    __syncthreads();
    if (threadIdx.x == 0) {
        __threadfence();
        const unsigned int my = g_bar_gen;
        const unsigned int arrived = atomicAdd(&g_bar_count, 1u);
        if (arrived == NBLK - 1) {
            g_bar_count = 0;
            __threadfence();
            g_bar_gen = my + 1;
        } else {
            while (g_bar_gen == my) { }
        }
        __threadfence();
    }
    __syncthreads();
}

__device__ __forceinline__ __half2 tanh2(__half2 x) {
    unsigned r, i = *reinterpret_cast<unsigned*>(&x);
    asm("tanh.approx.f16x2 %0, %1;" : "=r"(r) : "r"(i));
    return *reinterpret_cast<__half2*>(&r);
}
__device__ __forceinline__ float siluf(float x) {
    return __fdividef(x, 1.0f + __expf(-x));
}
__device__ __forceinline__ void cp16(unsigned int dst, const void* src) {
    asm volatile("cp.async.cg.shared.global [%0], [%1], 16;" :: "r"(dst), "l"(src));
}
#define CP_COMMIT()   asm volatile("cp.async.commit_group;")
#define CP_WAIT(n)    asm volatile("cp.async.wait_group %0;" :: "n"(n))

// ---------------------------------------------------------------------------
// ONE persistent kernel: 512 blocks x 256 threads, all resident (lb(256,4)).
// Phase 0: projection (2 rows/block) + W2c (blocks 0..127) + b2c (block 128)
// grid_barrier
// Phase 1: per (b, i-pair): fp16 weighted-silu accumulation over all 256 j
//          + fused epilogue.
// ---------------------------------------------------------------------------
__global__ void __launch_bounds__(256, 4) fused_kernel(
    const float* __restrict__ h,
    const float* __restrict__ adj,
    const float* __restrict__ W1a,
    const float* __restrict__ W1b,
    const float* __restrict__ b1,
    const float* __restrict__ W2,
    const float* __restrict__ b2,
    const float* __restrict__ Wc1,
    const float* __restrict__ bc1,
    const float* __restrict__ Wc2,
    const float* __restrict__ bc2,
    float* __restrict__ out)
{
    const int t    = threadIdx.x;
    const int blk  = blockIdx.x;       // 0..511
    const int lane = t & 31;
    const int w    = t >> 5;

    __shared__ uint4 ring4[8][4][32];  // 16KB (phase1 ring; overlaid later)
    __shared__ float adjsh[2][NN];     // 2KB
    __shared__ float wsum[2][8];
    __shared__ float sacc[2][MM];
    __shared__ float shid[2][MM];
    __shared__ float hsh[2][DD];       // phase 0
    __shared__ float red[MM];          // phase 0 (W2c reduce)

    // ================= Phase 0 =================
    {
        // projection: rows 2*blk, 2*blk+1
        hsh[t >> 7][t & 127] = h[(size_t)blk * 256 + t];
        __syncthreads();
        const int rg  = t >> 7;
        const int col = t & 127;
        float a = 0.f, p = 0.f;
        #pragma unroll 8
        for (int d = 0; d < DD; d++) {
            const float hv = hsh[rg][d];
            a = fmaf(hv, W1a[d * MM + col], a);
            p = fmaf(hv, W1b[d * MM + col], p);
        }
        const int row = blk * 2 + rg;
        g_pi[(size_t)row * MM + col]  = __float2half(0.5f * a);
        g_pjb[(size_t)row * MM + col] = __float2half(0.5f * (p + b1[col]));
    }
    if (blk < MM) {
        // W2c row 'blk': each thread does a 64-term half-dot, pair-reduce
        const int col = t & 127;
        const int hf  = t >> 7;
        float v = 0.f;
        const int l0 = hf * 64;
        #pragma unroll 8
        for (int l = l0; l < l0 + 64; l++)
            v = fmaf(W2[blk * MM + l], Wc1[l * MM + col], v);
        if (hf) red[col] = v;
        __syncthreads();
        if (!hf) g_W2c[blk * MM + col] = v + red[col];
    }
    if (blk == MM && t < MM) {
        float v = 0.f;
        #pragma unroll 8
        for (int l = 0; l < MM; l++)
            v = fmaf(b2[l], Wc1[l * MM + t], v);
        g_b2c[t] = v;
    }

    grid_barrier();

    // ================= Phase 1 =================
    const int b  = blk >> 7;
    const int i0 = (blk & 127) * 2;

    // adj rows for both i's; diagonal masked; row sums
    const float* arow0 = adj + ((size_t)(b * NN + i0)) * NN;
    const float* arow1 = arow0 + NN;
    float a0 = arow0[t], a1 = arow1[t];
    adjsh[0][t] = (t == i0)     ? 0.0f : a0;
    adjsh[1][t] = (t == i0 + 1) ? 0.0f : a1;
    const float ii0 = arow0[i0];
    const float ii1 = arow1[i0 + 1];
    #pragma unroll
    for (int o = 16; o; o >>= 1) {
        a0 += __shfl_xor_sync(0xFFFFFFFFu, a0, o);
        a1 += __shfl_xor_sync(0xFFFFFFFFu, a1, o);
    }
    if (lane == 0) { wsum[0][w] = a0; wsum[1][w] = a1; }
    __syncthreads();

    float sum0 = 0.f, sum1 = 0.f;
    #pragma unroll
    for (int g = 0; g < 8; g++) { sum0 += wsum[0][g]; sum1 += wsum[1][g]; }
    const float S0   = sum0 - ii0;
    const float S1   = sum1 - ii1;
    const float inv0 = __fdividef(1.0f, fmaxf(sum0, 1.0f));
    const float inv1 = __fdividef(1.0f, fmaxf(sum1, 1.0f));

    // pi for both i's: 8B per lane -> 2 half2 each
    __half2 piA0, piA1, piB0, piB1;
    {
        const unsigned long long* pA = reinterpret_cast<const unsigned long long*>(
            g_pi + ((size_t)(b * NN + i0)) * MM);
        const unsigned long long* pB = reinterpret_cast<const unsigned long long*>(
            g_pi + ((size_t)(b * NN + i0 + 1)) * MM);
        unsigned long long ra = pA[lane], rb = pB[lane];
        piA0 = *reinterpret_cast<__half2*>(&ra);
        piA1 = *(reinterpret_cast<__half2*>(&ra) + 1);
        piB0 = *reinterpret_cast<__half2*>(&rb);
        piB1 = *(reinterpret_cast<__half2*>(&rb) + 1);
    }

    // warp w owns 32 consecutive rows [w*32, w*32+32).
    // fp16 row = 256B; one slot (512B) = 2 rows; lane<16 -> even row chunks.
    const __half* srcbase = g_pjb + ((size_t)(b * NN) + w * 32) * MM
                            + (lane >> 4) * MM + (lane & 15) * 8;
    const unsigned int ring_lane =
        (unsigned int)__cvta_generic_to_shared(&ring4[w][0][0]) + lane * 16;
    const unsigned long long* rd =
        reinterpret_cast<const unsigned long long*>(&ring4[w][0][0]);
    const float* adjA = adjsh[0] + w * 32;
    const float* adjB = adjsh[1] + w * 32;

    float4 accA = make_float4(0.f, 0.f, 0.f, 0.f);
    float4 accB = make_float4(0.f, 0.f, 0.f, 0.f);

    // Prologue: 3 slots (6 rows) in flight
    #pragma unroll
    for (int s = 0; s < 3; s++) {
        cp16(ring_lane + s * 512, srcbase + s * 256);
        CP_COMMIT();
    }

    // 16 iterations x 2 rows, fully unrolled
    #pragma unroll
    for (int it = 0; it < 16; it++) {
        if (it <= 13)      { CP_WAIT(2); }
        else if (it == 14) { CP_WAIT(1); }
        else               { CP_WAIT(0); }

        #pragma unroll
        for (int rr = 0; rr < 2; rr++) {
            unsigned long long raw = rd[((it & 3) * 64) + rr * 32 + lane];
            const __half2 v0 = *reinterpret_cast<__half2*>(&raw);
            const __half2 v1 = *(reinterpret_cast<__half2*>(&raw) + 1);
            const float wA = adjA[2 * it + rr];
            const float wB = adjB[2 * it + rr];
            {
                __half2 hx0 = __hadd2(piA0, v0);
                __half2 hx1 = __hadd2(piA1, v1);
                __half2 s0 = __hfma2(hx0, tanh2(hx0), hx0);
                __half2 s1 = __hfma2(hx1, tanh2(hx1), hx1);
                float2 f0 = __half22float2(s0);
                float2 f1 = __half22float2(s1);
                accA.x = fmaf(wA, f0.x, accA.x);
                accA.y = fmaf(wA, f0.y, accA.y);
                accA.z = fmaf(wA, f1.x, accA.z);
                accA.w = fmaf(wA, f1.y, accA.w);
            }
            {
                __half2 hx0 = __hadd2(piB0, v0);
                __half2 hx1 = __hadd2(piB1, v1);
                __half2 s0 = __hfma2(hx0, tanh2(hx0), hx0);
                __half2 s1 = __hfma2(hx1, tanh2(hx1), hx1);
                float2 f0 = __half22float2(s0);
                float2 f1 = __half22float2(s1);
                accB.x = fmaf(wB, f0.x, accB.x);
                accB.y = fmaf(wB, f0.y, accB.y);
                accB.z = fmaf(wB, f1.x, accB.z);
                accB.w = fmaf(wB, f1.y, accB.w);
            }
        }

        if (it <= 12) {
            cp16(ring_lane + ((it + 3) & 3) * 512, srcbase + (it + 3) * 256);
            CP_COMMIT();
        }
    }

    // All ring reads done -> overlay acc-reduction buffer
    __syncthreads();
    float* accsh = reinterpret_cast<float*>(ring4);   // [8][2][MM]
    {
        float* myacc = accsh + w * 2 * MM;
        *reinterpret_cast<float4*>(myacc + lane * 4)      = accA;
        *reinterpret_cast<float4*>(myacc + MM + lane * 4) = accB;
    }
    __syncthreads();

    // Reduce across warps: thread -> (ii = t>>7, col = t&127)
    const int ii  = t >> 7;
    const int col = t & 127;
    {
        float s = 0.f;
        #pragma unroll
        for (int g = 0; g < 8; g++) s += accsh[g * 2 * MM + ii * MM + col];
        sacc[ii][col] = s;
    }
    __syncthreads();

    const float Si   = ii ? S1 : S0;
    const float invi = ii ? inv1 : inv0;

    // Stage 1: hid = silu((sacc @ W2c + S*b2c)*inv_d + bc1)  (coalesced cols)
    {
        const float* s = sacc[ii];
        float v0 = 0.f, v1 = 0.f, v2 = 0.f, v3 = 0.f;
        #pragma unroll 8
        for (int m2 = 0; m2 < MM; m2 += 4) {
            v0 = fmaf(s[m2],     g_W2c[m2 * MM + col],       v0);
            v1 = fmaf(s[m2 + 1], g_W2c[(m2 + 1) * MM + col], v1);
            v2 = fmaf(s[m2 + 2], g_W2c[(m2 + 2) * MM + col], v2);
            v3 = fmaf(s[m2 + 3], g_W2c[(m2 + 3) * MM + col], v3);
        }
        const float u = fmaf((v0 + v1) + (v2 + v3) + Si * g_b2c[col], invi, bc1[col]);
        shid[ii][col] = siluf(u);
    }
    __syncthreads();

    // Stage 2: out = hid @ Wc2 + bc2 (coalesced)
    {
        const float* hd = shid[ii];
        float v0 = bc2[col], v1 = 0.f, v2 = 0.f, v3 = 0.f;
        #pragma unroll 8
        for (int m2 = 0; m2 < MM; m2 += 4) {
            v0 = fmaf(hd[m2],     Wc2[m2 * CC + col],       v0);
            v1 = fmaf(hd[m2 + 1], Wc2[(m2 + 1) * CC + col], v1);
            v2 = fmaf(hd[m2 + 2], Wc2[(m2 + 2) * CC + col], v2);
            v3 = fmaf(hd[m2 + 3], Wc2[(m2 + 3) * CC + col], v3);
        }
        out[((size_t)(b * NN + i0 + ii)) * CC + col] = (v0 + v1) + (v2 + v3);
    }
}

// ---------------------------------------------------------------------------
// Launch
// ---------------------------------------------------------------------------
extern "C" void kernel_launch(void* const* d_in, const int* in_sizes, int n_in,
                              void* d_out, int out_size)
{
    const float* h   = (const float*)d_in[0];
    const float* adj = (const float*)d_in[1];
    const float* W1a = (const float*)d_in[2];
    const float* W1b = (const float*)d_in[3];
    const float* b1  = (const float*)d_in[4];
    const float* W2  = (const float*)d_in[5];
    const float* b2  = (const float*)d_in[6];
    const float* Wc1 = (const float*)d_in[7];
    const float* bc1 = (const float*)d_in[8];
    const float* Wc2 = (const float*)d_in[9];
    const float* bc2 = (const float*)d_in[10];
    float* out = (float*)d_out;

    fused_kernel<<<NBLK, 256>>>(h, adj, W1a, W1b, b1, W2, b2, Wc1,
                                bc1, Wc2, bc2, out);
}